// round 10
// baseline (speedup 1.0000x reference)
#include <cuda_runtime.h>
#include <cuda_bf16.h>
#include <math.h>
#include <stdint.h>

#define RB 4
#define CC 256
#define HWSZ 4096
#define OC2 18
#define PW 68
#define PHW 4624            // 68*68
#define PBASE 138           // 2*68 + 2

// ---------------- smem layout (bytes, dynamic) ------------------------------
// K-block 64. A tile 128oc x 64ck: hi 16KB @0, lo 16KB @16384.
#define SM_A    0
// B tile 128px x 64ck: hi 16KB @32768, lo 16KB @49152.
#define SM_B    32768
#define SM_IDX  65536       // int[1152]
#define SM_WY   70144       // float[1152]
#define SM_WX   74752       // float[1152]
#define SM_TOTAL 79360

// 128B-row swizzle (proven in R5)
#define SW(row, colb) (((uint32_t)(row) << 7) + \
    ((uint32_t)(colb) ^ (((uint32_t)(row) & 7) << 4)))

// ---------------- scratch ----------------------------------------------------
__device__ float g_padA[4734976];
__device__ float g_padB[4734976];
// main weights: [r][kb=kk*4+cb (36)][oc (256)][j (64)], c = cb*64+j
__device__ __align__(16) __nv_bfloat16 g_whi[2359296];
__device__ __align__(16) __nv_bfloat16 g_wlo[2359296];
// offset weights: [r][kb (36)][ocp (32)][j (64)]
__device__ __align__(16) __nv_bfloat16 g_owhi[294912];
__device__ __align__(16) __nv_bfloat16 g_owlo[294912];

// ---------------- PTX helpers ----------------------------------------------
static __device__ __forceinline__ uint32_t smem_u32(const void* p) {
    uint32_t a;
    asm("{ .reg .u64 t; cvta.to.shared.u64 t, %1; cvt.u32.u64 %0, t; }" : "=r"(a) : "l"(p));
    return a;
}

#define LDSM4(r, a) \
    asm volatile("ldmatrix.sync.aligned.m8n8.x4.shared.b16 {%0,%1,%2,%3}, [%4];" \
                 : "=r"((r)[0]), "=r"((r)[1]), "=r"((r)[2]), "=r"((r)[3]) : "r"(a))

#define MMA16816(c, a, b0, b1) \
    asm volatile("mma.sync.aligned.m16n8k16.row.col.f32.bf16.bf16.f32 " \
                 "{%0,%1,%2,%3}, {%4,%5,%6,%7}, {%8,%9}, {%0,%1,%2,%3};" \
                 : "+f"((c)[0]), "+f"((c)[1]), "+f"((c)[2]), "+f"((c)[3]) \
                 : "r"((a)[0]), "r"((a)[1]), "r"((a)[2]), "r"((a)[3]), \
                   "r"(b0), "r"(b1))

// ---------------- prep kernels ----------------------------------------------
__global__ void pad_input_kernel(const float* __restrict__ x,
                                 float* __restrict__ pA, float* __restrict__ pB) {
    int i = blockIdx.x * 256 + threadIdx.x;
    if (i >= 4734976) return;
    int plane = i / PHW, rem = i - plane * PHW;
    int h = rem / PW - 2, w = rem % PW - 2;
    float v = 0.f;
    if (h >= 0 && h < 64 && w >= 0 && w < 64) v = x[plane * HWSZ + h * 64 + w];
    pA[i] = v;
    pB[i] = 0.f;
}

__global__ void prep_w_kernel(const float* __restrict__ w,
                              __nv_bfloat16* __restrict__ whi,
                              __nv_bfloat16* __restrict__ wlo) {
    int idx = blockIdx.x * 256 + threadIdx.x;
    if (idx >= 2359296) return;
    int r = idx / 589824;
    int rem = idx - r * 589824;
    int kb = rem >> 14;
    int rem2 = rem & 16383;
    int oc = rem2 >> 6;
    int j = rem2 & 63;
    int kk = kb >> 2;
    int c = ((kb & 3) << 6) + j;
    float v = w[(((r * 256 + oc) * 256 + c) * 9) + kk];
    __nv_bfloat16 h = __float2bfloat16_rn(v);
    whi[idx] = h;
    wlo[idx] = __float2bfloat16_rn(v - __bfloat162float(h));
}

__global__ void prep_offw_kernel(const float* __restrict__ offw,
                                 __nv_bfloat16* __restrict__ owhi,
                                 __nv_bfloat16* __restrict__ owlo) {
    int idx = blockIdx.x * 256 + threadIdx.x;
    if (idx >= 294912) return;
    int r = idx / 73728;
    int rem = idx - r * 73728;
    int kb = rem >> 11;
    int rem2 = rem & 2047;
    int ocp = rem2 >> 6;
    int j = rem2 & 63;
    int kk = kb >> 2;
    int c = ((kb & 3) << 6) + j;
    float v = (ocp < OC2) ? offw[((r * OC2 + ocp) * 256 + c) * 9 + kk] : 0.f;
    __nv_bfloat16 h = __float2bfloat16_rn(v);
    owhi[idx] = h;
    owlo[idx] = __float2bfloat16_rn(v - __bfloat162float(h));
}

// ---------------- helpers ----------------------------------------------------
static __device__ __forceinline__ void cvt_pair(float v0, float v1,
        uint32_t& hp, uint32_t& lp) {
    __nv_bfloat162 h2, l2;
    h2.x = __float2bfloat16_rn(v0);
    h2.y = __float2bfloat16_rn(v1);
    l2.x = __float2bfloat16_rn(v0 - __bfloat162float(h2.x));
    l2.y = __float2bfloat16_rn(v1 - __bfloat162float(h2.y));
    hp = *(uint32_t*)&h2;
    lp = *(uint32_t*)&l2;
}

// ---------------- fused layer kernel ----------------------------------------
// grid = 256 CTAs (4 b x 2 oc-halves x 32 px-tiles), 256 threads / 8 warps.
// CTA tile: D[128 oc][128 px]; warp tile 64x32 (2M x 4N).
__global__ __launch_bounds__(256, 2) void fused_layer_kernel(
    const float* __restrict__ xpad,
    const __nv_bfloat16* __restrict__ owhi, const __nv_bfloat16* __restrict__ owlo,
    const float* __restrict__ offbias,
    const __nv_bfloat16* __restrict__ whi, const __nv_bfloat16* __restrict__ wlo,
    float* __restrict__ outp, int pad_out)
{
    extern __shared__ char smem[];
    uint32_t sb = smem_u32(smem);
    int tid = threadIdx.x;
    int lane = tid & 31;
    int wid = tid >> 5;
    int b = blockIdx.x >> 6;
    int oc_half = (blockIdx.x >> 5) & 1;
    int px0 = (blockIdx.x & 31) << 7;

    int px = tid & 127;
    int half = tid >> 7;          // 0/1: 32-channel half of the 64-ck block
    int hpx = (px0 + px) >> 6;
    int wpx = (px0 + px) & 63;

    // ================= PHASE 1: offset conv GEMM (D_off[32][128]) ==========
    float acc1[2][2][4];
#pragma unroll
    for (int mi = 0; mi < 2; ++mi)
#pragma unroll
        for (int nj = 0; nj < 2; ++nj)
#pragma unroll
            for (int q = 0; q < 4; ++q) acc1[mi][nj][q] = 0.f;

    int n_base1 = wid << 4;       // 16 px per warp

    for (int kb = 0; kb < 36; ++kb) {
        int kk = kb >> 2;
        if (kb) __syncthreads();

        // stage A_off hi/lo: 32 rows x 64 ck (4KB each), 1 chunk/thread
        {
            int row = tid >> 3, seg = tid & 7;
            uint32_t o = SW(row, seg << 4);
            *(uint4*)(smem + SM_A + o) =
                ((const uint4*)(owhi + ((size_t)kb << 11)))[tid];
            *(uint4*)(smem + SM_A + 16384 + o) =
                ((const uint4*)(owlo + ((size_t)kb << 11)))[tid];
        }

        // stage B im2col: [128 px][64 ck], this thread: 32 channels
        {
            const float* xb = xpad + ((size_t)(b * 256) + ((kb & 3) << 6) + (half << 5)) * PHW
                            + (hpx + kk / 3 + 1) * PW + (wpx + kk % 3 + 1);
#pragma unroll
            for (int ch = 0; ch < 4; ++ch) {
                uint32_t hp[4], lp[4];
#pragma unroll
                for (int jj = 0; jj < 4; ++jj) {
                    float v0 = xb[(size_t)(ch * 8 + jj * 2) * PHW];
                    float v1 = xb[(size_t)(ch * 8 + jj * 2 + 1) * PHW];
                    cvt_pair(v0, v1, hp[jj], lp[jj]);
                }
                uint32_t o = SW(px, (half << 6) + (ch << 4));
                *(uint4*)(smem + SM_B + o) = make_uint4(hp[0], hp[1], hp[2], hp[3]);
                *(uint4*)(smem + SM_B + 16384 + o) = make_uint4(lp[0], lp[1], lp[2], lp[3]);
            }
        }
        __syncthreads();

        // mma: 4 k16-steps; warp covers 32oc x 16px
#pragma unroll
        for (int ks = 0; ks < 4; ++ks) {
            uint32_t a1[2][4], bh[4], bl[4];
            int brow0 = n_base1 + ((lane >> 4) << 3) + (lane & 7);
            uint32_t bcolb = (uint32_t)((ks << 5) + (((lane >> 3) & 1) << 4));
            LDSM4(bh, sb + SM_B + SW(brow0, bcolb));
            LDSM4(bl, sb + SM_B + 16384 + SW(brow0, bcolb));
            int arow0 = lane & 15;
            uint32_t acolb = (uint32_t)((ks << 5) + ((lane >> 4) << 4));
#pragma unroll
            for (int mi = 0; mi < 2; ++mi)
                LDSM4(a1[mi], sb + SM_A + 16384 + SW(arow0 + (mi << 4), acolb)); // lo
#pragma unroll
            for (int mi = 0; mi < 2; ++mi)
#pragma unroll
                for (int nj = 0; nj < 2; ++nj)
                    MMA16816(acc1[mi][nj], a1[mi], bh[nj * 2], bh[nj * 2 + 1]);
#pragma unroll
            for (int mi = 0; mi < 2; ++mi)
                LDSM4(a1[mi], sb + SM_A + SW(arow0 + (mi << 4), acolb));         // hi
#pragma unroll
            for (int mi = 0; mi < 2; ++mi)
#pragma unroll
                for (int nj = 0; nj < 2; ++nj) {
                    MMA16816(acc1[mi][nj], a1[mi], bh[nj * 2], bh[nj * 2 + 1]);
                    MMA16816(acc1[mi][nj], a1[mi], bl[nj * 2], bl[nj * 2 + 1]);
                }
        }
    }
    __syncthreads();

    // write offsets to smem (reuse SM_B region): offs[32][128] f32
    {
        float* offs = (float*)(smem + SM_B);
#pragma unroll
        for (int mi = 0; mi < 2; ++mi)
#pragma unroll
            for (int nj = 0; nj < 2; ++nj) {
                int ocp = (mi << 4) + (lane >> 2);
                int pc = (wid << 4) + (nj << 3) + ((lane & 3) << 1);
                offs[ocp * 128 + pc] = acc1[mi][nj][0];
                offs[ocp * 128 + pc + 1] = acc1[mi][nj][1];
                offs[(ocp + 8) * 128 + pc] = acc1[mi][nj][2];
                offs[(ocp + 8) * 128 + pc + 1] = acc1[mi][nj][3];
            }
    }
    __syncthreads();

    // ---- bilinear metadata (padded addressing, clamped) ----
    {
        const float* offs = (const float*)(smem + SM_B);
        int* sIdx = (int*)(smem + SM_IDX);
        float* sWy = (float*)(smem + SM_WY);
        float* sWx = (float*)(smem + SM_WX);
        for (int i = tid; i < 1152; i += 256) {
            int kk = i >> 7;
            int p = i & 127;
            int pix = px0 + p;
            int h = pix >> 6;
            int w = pix & 63;
            float dy = offs[((2 * kk) << 7) + p] + offbias[2 * kk];
            float dx = offs[((2 * kk + 1) << 7) + p] + offbias[2 * kk + 1];
            float py = fminf(fmaxf((float)(h + kk / 3 - 1) + dy, -1.5f), 64.5f);
            float pxx = fminf(fmaxf((float)(w + kk % 3 - 1) + dx, -1.5f), 64.5f);
            float y0f = floorf(py), x0f = floorf(pxx);
            sIdx[i] = ((int)y0f + 2) * PW + ((int)x0f + 2);
            sWy[i] = py - y0f;
            sWx[i] = pxx - x0f;
        }
    }
    __syncthreads();

    // ================= PHASE 2: deform GEMM (D[128][128]) ==================
    float acc[4][4][4];
#pragma unroll
    for (int mi = 0; mi < 4; ++mi)
#pragma unroll
        for (int nj = 0; nj < 4; ++nj)
#pragma unroll
            for (int q = 0; q < 4; ++q) acc[mi][nj][q] = 0.f;

    int m_base = (wid & 1) << 6;
    int n_base = (wid >> 1) << 5;

    for (int kb = 0; kb < 36; ++kb) {
        int kk = kb >> 2;
        if (kb) __syncthreads();

        // stage A (weights, this oc-half) hi/lo: 128 rows x 64 ck
        {
            const uint4* ah = (const uint4*)(whi + ((size_t)kb << 14) + (oc_half << 13));
            const uint4* al = (const uint4*)(wlo + ((size_t)kb << 14) + (oc_half << 13));
#pragma unroll
            for (int t = 0; t < 4; ++t) {
                int i = tid + (t << 8);
                int row = i >> 3, seg = i & 7;
                uint32_t o = SW(row, seg << 4);
                *(uint4*)(smem + SM_A + o) = ah[i];
                *(uint4*)(smem + SM_A + 16384 + o) = al[i];
            }
        }

        // sample B tile: [128 px][64 ck], this thread: 32 channels
        {
            int mi_ = kk * 128 + px;
            int idx0 = ((const int*)(smem + SM_IDX))[mi_];
            float wy = ((const float*)(smem + SM_WY))[mi_];
            float wx = ((const float*)(smem + SM_WX))[mi_];
            float w01 = (1.f - wy) * wx;
            float w00 = (1.f - wy) - w01;
            float w11 = wy * wx;
            float w10 = wy - w11;
            const float* xb = xpad + ((size_t)(b * 256) + ((kb & 3) << 6) + (half << 5)) * PHW + idx0;
#pragma unroll
            for (int ch = 0; ch < 4; ++ch) {
                uint32_t hp[4], lp[4];
#pragma unroll
                for (int jj = 0; jj < 4; ++jj) {
                    const float* p0 = xb + (size_t)(ch * 8 + jj * 2) * PHW;
                    const float* p1 = p0 + PHW;
                    float v0 = fmaf(w11, p0[PW + 1], fmaf(w10, p0[PW], fmaf(w01, p0[1], w00 * p0[0])));
                    float v1 = fmaf(w11, p1[PW + 1], fmaf(w10, p1[PW], fmaf(w01, p1[1], w00 * p1[0])));
                    cvt_pair(v0, v1, hp[jj], lp[jj]);
                }
                uint32_t o = SW(px, (half << 6) + (ch << 4));
                *(uint4*)(smem + SM_B + o) = make_uint4(hp[0], hp[1], hp[2], hp[3]);
                *(uint4*)(smem + SM_B + 16384 + o) = make_uint4(lp[0], lp[1], lp[2], lp[3]);
            }
        }
        __syncthreads();

        // ldmatrix + mma: 4 k16-steps, combos al*bh, ah*bh, ah*bl
#pragma unroll
        for (int ks = 0; ks < 4; ++ks) {
            uint32_t a_[4][4], bf[2][4];
            int arow0 = m_base + (lane & 15);
            uint32_t acolb = (uint32_t)((ks << 5) + ((lane >> 4) << 4));
            int brow0 = n_base + ((lane >> 4) << 3) + (lane & 7);
            uint32_t bcolb = (uint32_t)((ks << 5) + (((lane >> 3) & 1) << 4));
#pragma unroll
            for (int np = 0; np < 2; ++np)
                LDSM4(bf[np], sb + SM_B + SW(brow0 + (np << 4), bcolb));         // B hi
#pragma unroll
            for (int mi = 0; mi < 4; ++mi)
                LDSM4(a_[mi], sb + SM_A + 16384 + SW(arow0 + (mi << 4), acolb)); // A lo
#pragma unroll
            for (int mi = 0; mi < 4; ++mi)
#pragma unroll
                for (int nj = 0; nj < 4; ++nj)
                    MMA16816(acc[mi][nj], a_[mi], bf[nj >> 1][(nj & 1) * 2], bf[nj >> 1][(nj & 1) * 2 + 1]);
#pragma unroll
            for (int mi = 0; mi < 4; ++mi)
                LDSM4(a_[mi], sb + SM_A + SW(arow0 + (mi << 4), acolb));         // A hi
#pragma unroll
            for (int mi = 0; mi < 4; ++mi)
#pragma unroll
                for (int nj = 0; nj < 4; ++nj)
                    MMA16816(acc[mi][nj], a_[mi], bf[nj >> 1][(nj & 1) * 2], bf[nj >> 1][(nj & 1) * 2 + 1]);
#pragma unroll
            for (int np = 0; np < 2; ++np)
                LDSM4(bf[np], sb + SM_B + 16384 + SW(brow0 + (np << 4), bcolb)); // B lo
#pragma unroll
            for (int mi = 0; mi < 4; ++mi)
#pragma unroll
                for (int nj = 0; nj < 4; ++nj)
                    MMA16816(acc[mi][nj], a_[mi], bf[nj >> 1][(nj & 1) * 2], bf[nj >> 1][(nj & 1) * 2 + 1]);
        }
    }

    // ---- epilogue: relu + direct v2 stores (padded or flat output) ----
    int plane = pad_out ? PHW : HWSZ;
    int ostride = pad_out ? PW : 64;
    int obase = pad_out ? PBASE : 0;
#pragma unroll
    for (int mi = 0; mi < 4; ++mi) {
#pragma unroll
        for (int nj = 0; nj < 4; ++nj) {
            int row = oc_half * 128 + m_base + (mi << 4) + (lane >> 2);
            int colp = n_base + (nj << 3) + ((lane & 3) << 1);
            int pix = px0 + colp;
            int h = pix >> 6;
            int wv = pix & 63;
            float* d0 = outp + (size_t)(b * 256 + row) * plane + h * ostride + wv + obase;
            float* d1 = outp + (size_t)(b * 256 + row + 8) * plane + h * ostride + wv + obase;
            float2 v0, v1;
            v0.x = fmaxf(acc[mi][nj][0], 0.f);
            v0.y = fmaxf(acc[mi][nj][1], 0.f);
            v1.x = fmaxf(acc[mi][nj][2], 0.f);
            v1.y = fmaxf(acc[mi][nj][3], 0.f);
            *(float2*)d0 = v0;
            *(float2*)d1 = v1;
        }
    }
}

// ---------------- launch ----------------------------------------------------
extern "C" void kernel_launch(void* const* d_in, const int* in_sizes, int n_in,
                              void* d_out, int out_size) {
    (void)in_sizes; (void)n_in; (void)out_size;
    const float* x    = (const float*)d_in[0];
    const float* offw = (const float*)d_in[1];
    const float* offb = (const float*)d_in[2];
    const float* w    = (const float*)d_in[3];
    float* out = (float*)d_out;

    float *padA, *padB;
    __nv_bfloat16 *gwhi, *gwlo, *gowhi, *gowlo;
    cudaGetSymbolAddress((void**)&padA, g_padA);
    cudaGetSymbolAddress((void**)&padB, g_padB);
    cudaGetSymbolAddress((void**)&gwhi, g_whi);
    cudaGetSymbolAddress((void**)&gwlo, g_wlo);
    cudaGetSymbolAddress((void**)&gowhi, g_owhi);
    cudaGetSymbolAddress((void**)&gowlo, g_owlo);

    cudaFuncSetAttribute(fused_layer_kernel,
                         cudaFuncAttributeMaxDynamicSharedMemorySize, SM_TOTAL);

    pad_input_kernel<<<(4734976 + 255) / 256, 256>>>(x, padA, padB);
    prep_w_kernel<<<(2359296 + 255) / 256, 256>>>(w, gwhi, gwlo);
    prep_offw_kernel<<<(294912 + 255) / 256, 256>>>(offw, gowhi, gowlo);

    const float* cur = padA;
    for (int r = 0; r < RB; ++r) {
        int last = (r == 3);
        float* nxt = last ? out : ((r & 1) == 0 ? padB : padA);
        fused_layer_kernel<<<256, 256, SM_TOTAL>>>(
            cur, gowhi + (size_t)r * 73728, gowlo + (size_t)r * 73728,
            offb + r * OC2, gwhi + (size_t)r * 589824, gwlo + (size_t)r * 589824,
            nxt, last ? 0 : 1);
        cur = nxt;
    }
}